// round 15
// baseline (speedup 1.0000x reference)
#include <cuda_runtime.h>
#include <cuda_bf16.h>
#include <cuda_fp16.h>
#include <cstdint>
#include <cstddef>

// Problem constants
#define BB 4
#define TT 2048
#define CC 1024
#define HH 16
#define HD 64
#define MM (BB * TT)          // 8192 rows
#define WSZ (CC * CC)

// ---------------- scratch (static device globals; no allocation) ----------------
#define ELEMS (BB * TT * CC)  // 8,388,608
__device__ __half g_xh[ELEMS];        // x: single fp16
__device__ __half g_qh[ELEMS];        // Q: single fp16 (pre-scaled by log2e/sqrt(HD))
__device__ __half g_kh[ELEMS];        // K: single fp16
__device__ __half g_vh[ELEMS];        // V: single fp16
__device__ __half g_yh[ELEMS];        // attention out (single fp16)
__device__ __half g_w[4 * CC * CC];   // weights: single fp16

// ================================================================================
// PTX helpers (base sm_103-safe: mma.sync / ldmatrix / cp.async only)
// ================================================================================
__device__ __forceinline__ uint32_t smem_u32(const void* p) {
    uint32_t a;
    asm("{ .reg .u64 t; cvta.to.shared.u64 t, %1; cvt.u32.u64 %0, t; }" : "=r"(a) : "l"(p));
    return a;
}

__device__ __forceinline__ void cp16(uint32_t dst, const void* src) {
    asm volatile("cp.async.cg.shared.global [%0], [%1], 16;" :: "r"(dst), "l"(src));
}
#define CP_COMMIT() asm volatile("cp.async.commit_group;" ::: "memory")
#define CP_WAIT(n)  asm volatile("cp.async.wait_group %0;" :: "n"(n) : "memory")

__device__ __forceinline__ void ldm_x4(uint32_t* r, uint32_t addr) {
    asm volatile("ldmatrix.sync.aligned.m8n8.x4.shared.b16 {%0,%1,%2,%3}, [%4];"
        : "=r"(r[0]), "=r"(r[1]), "=r"(r[2]), "=r"(r[3]) : "r"(addr));
}
__device__ __forceinline__ void ldm_x4_t(uint32_t* r, uint32_t addr) {
    asm volatile("ldmatrix.sync.aligned.m8n8.x4.trans.shared.b16 {%0,%1,%2,%3}, [%4];"
        : "=r"(r[0]), "=r"(r[1]), "=r"(r[2]), "=r"(r[3]) : "r"(addr));
}

__device__ __forceinline__ void mma_f16(float* d, const uint32_t* a,
                                        uint32_t b0, uint32_t b1) {
    asm volatile(
        "mma.sync.aligned.m16n8k16.row.col.f32.f16.f16.f32 "
        "{%0,%1,%2,%3}, {%4,%5,%6,%7}, {%8,%9}, {%0,%1,%2,%3};"
        : "+f"(d[0]), "+f"(d[1]), "+f"(d[2]), "+f"(d[3])
        : "r"(a[0]), "r"(a[1]), "r"(a[2]), "r"(a[3]), "r"(b0), "r"(b1));
}

// raw EX2 (arguments are pre-scaled into log2 domain)
__device__ __forceinline__ float ex2(float x) {
    float y;
    asm("ex2.approx.ftz.f32 %0, %1;" : "=f"(y) : "f"(x));
    return y;
}

// SW128 swizzle on a 128B-row tile
#define SWZ(row, kbyte) (((row) << 7) + ((kbyte) ^ (((row) & 7) << 4)))

// fp16 pack helper
__device__ __forceinline__ uint32_t packh2(float x, float y) {
    __half2 p = __floats2half2_rn(x, y);
    return *reinterpret_cast<uint32_t*>(&p);
}

// Q pre-scale: log2(e) / sqrt(HD) so attention can use raw ex2
#define QSCALE 0.1803368801111204f

// ================================================================================
// Merged fp32 -> fp16 conversion: x + all 4 weight matrices, ONE launch.
// ================================================================================
#define NB_X (ELEMS / 4 / 256)     // 8192 blocks for x
#define NB_W (WSZ / 4 / 256)       // 1024 blocks per weight
#define NB_ALL (NB_X + 4 * NB_W)   // 12288

__global__ __launch_bounds__(256) void conv_all_kernel(
    const float* __restrict__ x,
    const float* __restrict__ w0, const float* __restrict__ w1,
    const float* __restrict__ w2, const float* __restrict__ w3,
    __half* __restrict__ xh, __half* __restrict__ wdst)
{
    const int bx = blockIdx.x;
    const float* src;
    __half* dst;
    int i;
    if (bx < NB_X) {
        src = x; dst = xh;
        i = bx * 256 + threadIdx.x;
    } else {
        const int m = (bx - NB_X) >> 10;
        const int bw = (bx - NB_X) & 1023;
        src = (m == 0) ? w0 : (m == 1) ? w1 : (m == 2) ? w2 : w3;
        dst = wdst + (size_t)m * WSZ;
        i = bw * 256 + threadIdx.x;
    }
    float4 v = ((const float4*)src)[i];
    ((uint32_t*)dst)[2 * i + 0] = packh2(v.x, v.y);
    ((uint32_t*)dst)[2 * i + 1] = packh2(v.z, v.w);
}

// ================================================================================
// GEMM core loop config: 128x128 tile/CTA, 8 warps as 8 m16-strips x n128,
// K-chunk 64, cp.async double-buffered (2 CTAs/SM). 9 LDSM per 32 MMA per k16.
// ================================================================================
#define KC 64
#define NCHUNK (CC / KC)      // 16
#define TILE_B 16384          // 128 rows x 128B (64 fp16)
#define SMEM_G (2 * 2 * TILE_B)   // 65536

// ================================================================================
// Fused QKV projection GEMM (1-term fp16): one launch for all three matrices.
// blockIdx.x in [0,24): mat = bx>>3, n-tile = bx&7. Output: fp16 single, scaled.
// ================================================================================
__global__ __launch_bounds__(256) void qkv_mma_kernel(
    const __half* __restrict__ xh, const __half* __restrict__ w,
    const float* __restrict__ bq, const float* __restrict__ bk,
    const float* __restrict__ bv,
    __half* __restrict__ qh, __half* __restrict__ kh, __half* __restrict__ vh)
{
    extern __shared__ char smem[];
    const uint32_t sbase = smem_u32(smem);
    const int tid = threadIdx.x;
    const int wid = tid >> 5;      // m-strip 0..7
    const int lane = tid & 31;

    const int mat = blockIdx.x >> 3;
    const int bn = (blockIdx.x & 7) * 128;
    const int bm = blockIdx.y * 128;

    const __half* B = w + (size_t)mat * WSZ;
    const float* bias = (mat == 0) ? bq : (mat == 1) ? bk : bv;
    __half* out = (mat == 0) ? qh : (mat == 1) ? kh : vh;
    const float scale = (mat == 0) ? QSCALE : 1.0f;

    const int lrow = (lane & 7) + ((lane >> 3) & 1) * 8;
    const int lkb = (lane >> 4) * 16;

    float acc[16][4];                      // m16 x n128 per warp
#pragma unroll
    for (int a = 0; a < 16; a++)
#pragma unroll
        for (int c = 0; c < 4; c++) acc[a][c] = 0.0f;

    auto load_chunk = [&](int chunk, int buf) {
        const int k0 = chunk * KC;
        const uint32_t tbu = sbase + buf * 2 * TILE_B;
#pragma unroll
        for (int part = 0; part < 2; part++) {
            const __half* p = part ? B : xh;
            const int roff = part ? bn : bm;
            const uint32_t db = tbu + part * TILE_B;
#pragma unroll
            for (int f = tid; f < 1024; f += 256) {
                int row = f >> 3;
                int c16 = f & 7;
                cp16(db + SWZ(row, c16 * 16),
                     p + (size_t)(roff + row) * CC + k0 + c16 * 8);
            }
        }
        CP_COMMIT();
    };

    load_chunk(0, 0);

    for (int chunk = 0; chunk < NCHUNK; chunk++) {
        const int buf = chunk & 1;
        if (chunk + 1 < NCHUNK) {
            load_chunk(chunk + 1, buf ^ 1);
            CP_WAIT(1);
        } else {
            CP_WAIT(0);
        }
        __syncthreads();

        const uint32_t tA = sbase + buf * 2 * TILE_B;
        const uint32_t tB = tA + TILE_B;

#pragma unroll
        for (int ks = 0; ks < 4; ks++) {
            const int kb = ks * 32;
            uint32_t af[4];
            ldm_x4(af, tA + SWZ(wid * 16 + lrow, kb + lkb));
            // two half-groups of 4 B-fragments to cap register liveness
#pragma unroll
            for (int nh = 0; nh < 2; nh++) {
                uint32_t bf[4][4];
#pragma unroll
                for (int nj2 = 0; nj2 < 4; nj2++)
                    ldm_x4(bf[nj2], tB + SWZ(nh * 64 + nj2 * 16 + lrow, kb + lkb));
#pragma unroll
                for (int nj2 = 0; nj2 < 4; nj2++) {
#pragma unroll
                    for (int hh = 0; hh < 2; hh++) {
                        mma_f16(acc[nh * 8 + nj2 * 2 + hh], af,
                                bf[nj2][hh], bf[nj2][hh + 2]);
                    }
                }
            }
        }
        __syncthreads();
    }

    // epilogue: bias, scale, fp16 single out; warp = m16 strip, all 128 cols
    const int lr = lane >> 2;
    const int lc = (lane & 3) * 2;
    const int r = bm + wid * 16 + lr;
#pragma unroll
    for (int nj = 0; nj < 16; nj++) {
        const int c = bn + nj * 8 + lc;
        const float b0 = bias[c], b1 = bias[c + 1];
        float v0 = acc[nj][0] + b0, v1 = acc[nj][1] + b1;
        float v2 = acc[nj][2] + b0, v3 = acc[nj][3] + b1;
        *(uint32_t*)&out[(size_t)r * CC + c] = packh2(v0 * scale, v1 * scale);
        *(uint32_t*)&out[(size_t)(r + 8) * CC + c] = packh2(v2 * scale, v3 * scale);
    }
}

// ================================================================================
// Output projection GEMM: 1-term fp16, yh @ Wp^T -> fp32 out. Same warp remap.
// ================================================================================
__global__ __launch_bounds__(256) void proj_mma_kernel(
    const __half* __restrict__ Ah, const __half* __restrict__ B,
    float* __restrict__ Cf)
{
    extern __shared__ char smem[];
    const uint32_t sbase = smem_u32(smem);
    const int tid = threadIdx.x;
    const int wid = tid >> 5;
    const int lane = tid & 31;
    const int bm = blockIdx.y * 128;
    const int bn = blockIdx.x * 128;

    const int lrow = (lane & 7) + ((lane >> 3) & 1) * 8;
    const int lkb = (lane >> 4) * 16;

    float acc[16][4];
#pragma unroll
    for (int a = 0; a < 16; a++)
#pragma unroll
        for (int c = 0; c < 4; c++) acc[a][c] = 0.0f;

    auto load_chunk = [&](int chunk, int buf) {
        const int k0 = chunk * KC;
        const uint32_t tbu = sbase + buf * 2 * TILE_B;
#pragma unroll
        for (int part = 0; part < 2; part++) {
            const __half* p = part ? B : Ah;
            const int roff = part ? bn : bm;
            const uint32_t db = tbu + part * TILE_B;
#pragma unroll
            for (int f = tid; f < 1024; f += 256) {
                int row = f >> 3;
                int c16 = f & 7;
                cp16(db + SWZ(row, c16 * 16),
                     p + (size_t)(roff + row) * CC + k0 + c16 * 8);
            }
        }
        CP_COMMIT();
    };

    load_chunk(0, 0);

    for (int chunk = 0; chunk < NCHUNK; chunk++) {
        const int buf = chunk & 1;
        if (chunk + 1 < NCHUNK) {
            load_chunk(chunk + 1, buf ^ 1);
            CP_WAIT(1);
        } else {
            CP_WAIT(0);
        }
        __syncthreads();

        const uint32_t tA = sbase + buf * 2 * TILE_B;
        const uint32_t tB = tA + TILE_B;

#pragma unroll
        for (int ks = 0; ks < 4; ks++) {
            const int kb = ks * 32;
            uint32_t af[4];
            ldm_x4(af, tA + SWZ(wid * 16 + lrow, kb + lkb));
#pragma unroll
            for (int nh = 0; nh < 2; nh++) {
                uint32_t bf[4][4];
#pragma unroll
                for (int nj2 = 0; nj2 < 4; nj2++)
                    ldm_x4(bf[nj2], tB + SWZ(nh * 64 + nj2 * 16 + lrow, kb + lkb));
#pragma unroll
                for (int nj2 = 0; nj2 < 4; nj2++) {
#pragma unroll
                    for (int hh = 0; hh < 2; hh++) {
                        mma_f16(acc[nh * 8 + nj2 * 2 + hh], af,
                                bf[nj2][hh], bf[nj2][hh + 2]);
                    }
                }
            }
        }
        __syncthreads();
    }

    const int lr = lane >> 2;
    const int lc = (lane & 3) * 2;
    const int r = bm + wid * 16 + lr;
#pragma unroll
    for (int nj = 0; nj < 16; nj++) {
        const int c = bn + nj * 8 + lc;
        *(float2*)&Cf[(size_t)r * CC + c] = make_float2(acc[nj][0], acc[nj][1]);
        *(float2*)&Cf[(size_t)(r + 8) * CC + c] = make_float2(acc[nj][2], acc[nj][3]);
    }
}

// ================================================================================
// Flash attention via mma.sync, all-single fp16 operands (Q, K, V, P).
// Q is pre-scaled into log2 domain -> softmax uses raw ex2. (champion verbatim)
// ================================================================================
#define ATT_SMEM 49152

__global__ __launch_bounds__(256) void attn_mma_kernel(
    const __half* __restrict__ qh, const __half* __restrict__ kh,
    const __half* __restrict__ vh, __half* __restrict__ yh)
{
    extern __shared__ char smem[];
    const uint32_t sb = smem_u32(smem);
    const uint32_t sQ = sb;
    const uint32_t sKV = sb + 16384;   // + buf*16384: K@0, V@8192

    const int tid = threadIdx.x;
    const int wid = tid >> 5;
    const int lane = tid & 31;
    const int lrow = (lane & 7) + ((lane >> 3) & 1) * 8;
    const int lkb = (lane >> 4) * 16;

    // heavy-first: largest qt launches earliest
    const int qt = (gridDim.x - 1) - blockIdx.x;
    const int q0 = qt * 128;
    const int bh = blockIdx.y;
    const int b = bh >> 4;
    const int h = bh & 15;
    const size_t base = (size_t)b * TT * CC + (size_t)h * HD;

#pragma unroll
    for (int f = tid; f < 1024; f += 256) {
        int row = f >> 3, c16 = f & 7;
        cp16(sQ + SWZ(row, c16 * 16), qh + base + (size_t)(q0 + row) * CC + c16 * 8);
    }

    const __half* kvsrc[2] = {kh, vh};
    auto load_kv = [&](int kt, int buf) {
        const uint32_t db = sKV + buf * 16384;
#pragma unroll
        for (int f = tid; f < 1024; f += 256) {
            int mat = f >> 9, idx = f & 511;
            int row = idx >> 3, c16 = idx & 7;
            cp16(db + mat * 8192 + SWZ(row, c16 * 16),
                 kvsrc[mat] + base + (size_t)(kt * 64 + row) * CC + c16 * 8);
        }
    };

    const int nkt = 2 * (qt + 1);
    load_kv(0, 0);
    CP_COMMIT();

    float m0 = -3.0e38f, m1 = -3.0e38f, l0 = 0.0f, l1 = 0.0f;
    float o[8][4];
#pragma unroll
    for (int nt = 0; nt < 8; nt++)
#pragma unroll
        for (int c = 0; c < 4; c++) o[nt][c] = 0.0f;

    const int q0w = q0 + 16 * wid;

    for (int kt = 0; kt < nkt; kt++) {
        const int buf = kt & 1;
        if (kt + 1 < nkt) {
            load_kv(kt + 1, buf ^ 1);
            CP_COMMIT();
            CP_WAIT(1);
        } else {
            CP_WAIT(0);
        }
        __syncthreads();

        const int kc = kt * 64;
        if (kc <= q0w + 15) {
            const uint32_t bK = sKV + buf * 16384;
            const uint32_t bV = bK + 8192;

            // ---- S = Q K^T (single fp16, log2 domain) ----
            float s[8][4];
#pragma unroll
            for (int nt = 0; nt < 8; nt++)
#pragma unroll
                for (int c = 0; c < 4; c++) s[nt][c] = 0.0f;

#pragma unroll
            for (int ks = 0; ks < 4; ks++) {
                const int kb = ks * 32;
                uint32_t a[4];
                ldm_x4(a, sQ + SWZ(16 * wid + lrow, kb + lkb));
#pragma unroll
                for (int nt2 = 0; nt2 < 4; nt2++) {
                    uint32_t bhf[4];
                    ldm_x4(bhf, bK + SWZ(nt2 * 16 + lrow, kb + lkb));
#pragma unroll
                    for (int hh = 0; hh < 2; hh++) {
                        mma_f16(s[nt2 * 2 + hh], a, bhf[hh], bhf[hh + 2]);
                    }
                }
            }

            // ---- causal mask on diagonal tiles ----
            if (kc + 63 > q0w) {
                const int r0 = q0w + (lane >> 2);
                const int r1 = r0 + 8;
#pragma unroll
                for (int nt = 0; nt < 8; nt++) {
                    int c0 = kc + 8 * nt + 2 * (lane & 3);
                    if (c0 > r0)     s[nt][0] = -1.0e30f;
                    if (c0 + 1 > r0) s[nt][1] = -1.0e30f;
                    if (c0 > r1)     s[nt][2] = -1.0e30f;
                    if (c0 + 1 > r1) s[nt][3] = -1.0e30f;
                }
            }

            // ---- online softmax (ex2; s already in log2 domain) ----
            float mt0 = -3.0e38f, mt1 = -3.0e38f;
#pragma unroll
            for (int nt = 0; nt < 8; nt++) {
                mt0 = fmaxf(mt0, fmaxf(s[nt][0], s[nt][1]));
                mt1 = fmaxf(mt1, fmaxf(s[nt][2], s[nt][3]));
            }
#pragma unroll
            for (int d = 1; d <= 2; d <<= 1) {
                mt0 = fmaxf(mt0, __shfl_xor_sync(0xffffffffu, mt0, d));
                mt1 = fmaxf(mt1, __shfl_xor_sync(0xffffffffu, mt1, d));
            }
            float mn0 = fmaxf(m0, mt0), mn1 = fmaxf(m1, mt1);
            float corr0 = ex2(m0 - mn0), corr1 = ex2(m1 - mn1);
            float ls0 = 0.0f, ls1 = 0.0f;
#pragma unroll
            for (int nt = 0; nt < 8; nt++) {
                s[nt][0] = ex2(s[nt][0] - mn0);
                s[nt][1] = ex2(s[nt][1] - mn0);
                s[nt][2] = ex2(s[nt][2] - mn1);
                s[nt][3] = ex2(s[nt][3] - mn1);
                ls0 += s[nt][0] + s[nt][1];
                ls1 += s[nt][2] + s[nt][3];
            }
#pragma unroll
            for (int d = 1; d <= 2; d <<= 1) {
                ls0 += __shfl_xor_sync(0xffffffffu, ls0, d);
                ls1 += __shfl_xor_sync(0xffffffffu, ls1, d);
            }
            l0 = l0 * corr0 + ls0;  m0 = mn0;
            l1 = l1 * corr1 + ls1;  m1 = mn1;
#pragma unroll
            for (int nt = 0; nt < 8; nt++) {
                o[nt][0] *= corr0; o[nt][1] *= corr0;
                o[nt][2] *= corr1; o[nt][3] *= corr1;
            }

            // ---- O += P V (single fp16) ----
#pragma unroll
            for (int ks = 0; ks < 4; ks++) {
                uint32_t a[4];
                a[0] = packh2(s[2 * ks][0], s[2 * ks][1]);
                a[1] = packh2(s[2 * ks][2], s[2 * ks][3]);
                a[2] = packh2(s[2 * ks + 1][0], s[2 * ks + 1][1]);
                a[3] = packh2(s[2 * ks + 1][2], s[2 * ks + 1][3]);
#pragma unroll
                for (int nt2 = 0; nt2 < 4; nt2++) {
                    uint32_t bvh[4];
                    ldm_x4_t(bvh, bV + SWZ(ks * 16 + lrow, nt2 * 32 + lkb));
#pragma unroll
                    for (int hh = 0; hh < 2; hh++) {
                        mma_f16(o[nt2 * 2 + hh], a, bvh[2 * hh], bvh[2 * hh + 1]);
                    }
                }
            }
        }
        __syncthreads();
    }

    // ---- normalize, store single fp16 ----
    const float inv0 = 1.0f / l0, inv1 = 1.0f / l1;
    const int t0 = q0w + (lane >> 2);
    const int t1 = t0 + 8;
#pragma unroll
    for (int nt = 0; nt < 8; nt++) {
        const int c = 8 * nt + 2 * (lane & 3);
        *(uint32_t*)&yh[base + (size_t)t0 * CC + c] =
            packh2(o[nt][0] * inv0, o[nt][1] * inv0);
        *(uint32_t*)&yh[base + (size_t)t1 * CC + c] =
            packh2(o[nt][2] * inv1, o[nt][3] * inv1);
    }
}

// ================================================================================
// launch
// ================================================================================
extern "C" void kernel_launch(void* const* d_in, const int* in_sizes, int n_in,
                              void* d_out, int out_size)
{
    const float* x  = (const float*)d_in[0];
    const float* Wq = (const float*)d_in[1];
    const float* bq = (const float*)d_in[2];
    const float* Wk = (const float*)d_in[3];
    const float* bk = (const float*)d_in[4];
    const float* Wv = (const float*)d_in[5];
    const float* bv = (const float*)d_in[6];
    const float* Wp = (const float*)d_in[7];
    float* out = (float*)d_out;

    __half *xh, *qh, *kh, *vh, *yh, *w;
    cudaGetSymbolAddress((void**)&xh, g_xh);
    cudaGetSymbolAddress((void**)&qh, g_qh);
    cudaGetSymbolAddress((void**)&kh, g_kh);
    cudaGetSymbolAddress((void**)&vh, g_vh);
    cudaGetSymbolAddress((void**)&yh, g_yh);
    cudaGetSymbolAddress((void**)&w,  g_w);

    cudaFuncSetAttribute(qkv_mma_kernel, cudaFuncAttributeMaxDynamicSharedMemorySize,
                         SMEM_G);
    cudaFuncSetAttribute(proj_mma_kernel, cudaFuncAttributeMaxDynamicSharedMemorySize,
                         SMEM_G);
    cudaFuncSetAttribute(attn_mma_kernel, cudaFuncAttributeMaxDynamicSharedMemorySize,
                         ATT_SMEM);

    // merged conversions: x + all 4 weights in ONE launch
    conv_all_kernel<<<NB_ALL, 256>>>(x, Wq, Wk, Wv, Wp, xh, w);

    // fused QKV projections: 128x128, 2-stage, warp = m16 x n128 strips
    qkv_mma_kernel<<<dim3(24, MM / 128), 256, SMEM_G>>>(xh, w, bq, bk, bv,
                                                        qh, kh, vh);

    // attention (tensor-core fp16, heavy-first, ex2 softmax) — champion verbatim
    attn_mma_kernel<<<dim3(TT / 128, BB * HH), 256, ATT_SMEM>>>(qh, kh, vh, yh);

    // output projection: 128x128, 2-stage, warp = m16 x n128 strips
    proj_mma_kernel<<<dim3(CC / 128, MM / 128), 256, SMEM_G>>>(yh, w + 3 * WSZ, out);
}

// round 16
// speedup vs baseline: 1.0256x; 1.0256x over previous
#include <cuda_runtime.h>
#include <cuda_bf16.h>
#include <cuda_fp16.h>
#include <cstdint>
#include <cstddef>

// Problem constants
#define BB 4
#define TT 2048
#define CC 1024
#define HH 16
#define HD 64
#define MM (BB * TT)          // 8192 rows
#define WSZ (CC * CC)

// ---------------- scratch (static device globals; no allocation) ----------------
#define ELEMS (BB * TT * CC)  // 8,388,608
__device__ __half g_xh[ELEMS];        // x: single fp16
__device__ __half g_qh[ELEMS];        // Q: single fp16 (pre-scaled by log2e/sqrt(HD))
__device__ __half g_kh[ELEMS];        // K: single fp16
__device__ __half g_vh[ELEMS];        // V: single fp16
__device__ __half g_yh[ELEMS];        // attention out (single fp16)
__device__ __half g_w[4 * CC * CC];   // weights: single fp16

// ================================================================================
// PTX helpers (base sm_103-safe: mma.sync / ldmatrix / cp.async only)
// ================================================================================
__device__ __forceinline__ uint32_t smem_u32(const void* p) {
    uint32_t a;
    asm("{ .reg .u64 t; cvta.to.shared.u64 t, %1; cvt.u32.u64 %0, t; }" : "=r"(a) : "l"(p));
    return a;
}

__device__ __forceinline__ void cp16(uint32_t dst, const void* src) {
    asm volatile("cp.async.cg.shared.global [%0], [%1], 16;" :: "r"(dst), "l"(src));
}
#define CP_COMMIT() asm volatile("cp.async.commit_group;" ::: "memory")
#define CP_WAIT(n)  asm volatile("cp.async.wait_group %0;" :: "n"(n) : "memory")

__device__ __forceinline__ void ldm_x4(uint32_t* r, uint32_t addr) {
    asm volatile("ldmatrix.sync.aligned.m8n8.x4.shared.b16 {%0,%1,%2,%3}, [%4];"
        : "=r"(r[0]), "=r"(r[1]), "=r"(r[2]), "=r"(r[3]) : "r"(addr));
}
__device__ __forceinline__ void ldm_x4_t(uint32_t* r, uint32_t addr) {
    asm volatile("ldmatrix.sync.aligned.m8n8.x4.trans.shared.b16 {%0,%1,%2,%3}, [%4];"
        : "=r"(r[0]), "=r"(r[1]), "=r"(r[2]), "=r"(r[3]) : "r"(addr));
}

__device__ __forceinline__ void mma_f16(float* d, const uint32_t* a,
                                        uint32_t b0, uint32_t b1) {
    asm volatile(
        "mma.sync.aligned.m16n8k16.row.col.f32.f16.f16.f32 "
        "{%0,%1,%2,%3}, {%4,%5,%6,%7}, {%8,%9}, {%0,%1,%2,%3};"
        : "+f"(d[0]), "+f"(d[1]), "+f"(d[2]), "+f"(d[3])
        : "r"(a[0]), "r"(a[1]), "r"(a[2]), "r"(a[3]), "r"(b0), "r"(b1));
}

// raw EX2 (arguments are pre-scaled into log2 domain)
__device__ __forceinline__ float ex2(float x) {
    float y;
    asm("ex2.approx.ftz.f32 %0, %1;" : "=f"(y) : "f"(x));
    return y;
}

// SW128 swizzle on a 128B-row tile
#define SWZ(row, kbyte) (((row) << 7) + ((kbyte) ^ (((row) & 7) << 4)))

// fp16 pack helper
__device__ __forceinline__ uint32_t packh2(float x, float y) {
    __half2 p = __floats2half2_rn(x, y);
    return *reinterpret_cast<uint32_t*>(&p);
}

// Q pre-scale: log2(e) / sqrt(HD) so attention can use raw ex2
#define QSCALE 0.1803368801111204f

// ================================================================================
// Merged fp32 -> fp16 conversion: x + all 4 weight matrices, ONE launch.
// ================================================================================
#define NB_X (ELEMS / 4 / 256)     // 8192 blocks for x
#define NB_W (WSZ / 4 / 256)       // 1024 blocks per weight
#define NB_ALL (NB_X + 4 * NB_W)   // 12288

__global__ __launch_bounds__(256) void conv_all_kernel(
    const float* __restrict__ x,
    const float* __restrict__ w0, const float* __restrict__ w1,
    const float* __restrict__ w2, const float* __restrict__ w3,
    __half* __restrict__ xh, __half* __restrict__ wdst)
{
    const int bx = blockIdx.x;
    const float* src;
    __half* dst;
    int i;
    if (bx < NB_X) {
        src = x; dst = xh;
        i = bx * 256 + threadIdx.x;
    } else {
        const int m = (bx - NB_X) >> 10;
        const int bw = (bx - NB_X) & 1023;
        src = (m == 0) ? w0 : (m == 1) ? w1 : (m == 2) ? w2 : w3;
        dst = wdst + (size_t)m * WSZ;
        i = bw * 256 + threadIdx.x;
    }
    float4 v = ((const float4*)src)[i];
    ((uint32_t*)dst)[2 * i + 0] = packh2(v.x, v.y);
    ((uint32_t*)dst)[2 * i + 1] = packh2(v.z, v.w);
}

// ================================================================================
// GEMM config: 128x128 tile/CTA, K-chunk 64, cp.async double-buffered, 2 CTAs/SM.
// ================================================================================
#define KC 64
#define NCHUNK (CC / KC)      // 16
#define TILE_B 16384          // 128 rows x 128B (64 fp16)
#define SMEM_G (2 * 2 * TILE_B)   // 65536

// ================================================================================
// Fused QKV projection GEMM (1-term fp16): R14 champion — 8 warps (2m x 4n),
// warp tile 64x32. blockIdx.x in [0,24): mat = bx>>3, n-tile = bx&7.
// ================================================================================
__global__ __launch_bounds__(256) void qkv_mma_kernel(
    const __half* __restrict__ xh, const __half* __restrict__ w,
    const float* __restrict__ bq, const float* __restrict__ bk,
    const float* __restrict__ bv,
    __half* __restrict__ qh, __half* __restrict__ kh, __half* __restrict__ vh)
{
    extern __shared__ char smem[];
    const uint32_t sbase = smem_u32(smem);
    const int tid = threadIdx.x;
    const int wid = tid >> 5;
    const int lane = tid & 31;
    const int wm = wid & 1;
    const int wn = wid >> 1;

    const int mat = blockIdx.x >> 3;
    const int bn = (blockIdx.x & 7) * 128;
    const int bm = blockIdx.y * 128;

    const __half* B = w + (size_t)mat * WSZ;
    const float* bias = (mat == 0) ? bq : (mat == 1) ? bk : bv;
    __half* out = (mat == 0) ? qh : (mat == 1) ? kh : vh;
    const float scale = (mat == 0) ? QSCALE : 1.0f;

    const int lrow = (lane & 7) + ((lane >> 3) & 1) * 8;
    const int lkb = (lane >> 4) * 16;

    float acc[4][4][4];
#pragma unroll
    for (int a = 0; a < 4; a++)
#pragma unroll
        for (int b = 0; b < 4; b++)
#pragma unroll
            for (int c = 0; c < 4; c++) acc[a][b][c] = 0.0f;

    auto load_chunk = [&](int chunk, int buf) {
        const int k0 = chunk * KC;
        const uint32_t tbu = sbase + buf * 2 * TILE_B;
#pragma unroll
        for (int part = 0; part < 2; part++) {
            const __half* p = part ? B : xh;
            const int roff = part ? bn : bm;
            const uint32_t db = tbu + part * TILE_B;
#pragma unroll
            for (int f = tid; f < 1024; f += 256) {
                int row = f >> 3;
                int c16 = f & 7;
                cp16(db + SWZ(row, c16 * 16),
                     p + (size_t)(roff + row) * CC + k0 + c16 * 8);
            }
        }
        CP_COMMIT();
    };

    load_chunk(0, 0);

    for (int chunk = 0; chunk < NCHUNK; chunk++) {
        const int buf = chunk & 1;
        if (chunk + 1 < NCHUNK) {
            load_chunk(chunk + 1, buf ^ 1);
            CP_WAIT(1);
        } else {
            CP_WAIT(0);
        }
        __syncthreads();

        const uint32_t tA = sbase + buf * 2 * TILE_B;
        const uint32_t tB = tA + TILE_B;

#pragma unroll
        for (int ks = 0; ks < 4; ks++) {
            const int kb = ks * 32;
            uint32_t ah[4][4], bf[2][4];
#pragma unroll
            for (int mi = 0; mi < 4; mi++) {
                int row = wm * 64 + mi * 16 + lrow;
                ldm_x4(ah[mi], tA + SWZ(row, kb + lkb));
            }
#pragma unroll
            for (int nj2 = 0; nj2 < 2; nj2++) {
                int row = wn * 32 + nj2 * 16 + lrow;
                ldm_x4(bf[nj2], tB + SWZ(row, kb + lkb));
            }
#pragma unroll
            for (int mi = 0; mi < 4; mi++) {
#pragma unroll
                for (int nj = 0; nj < 4; nj++) {
                    const int h = nj & 1;
                    mma_f16(acc[mi][nj], ah[mi], bf[nj >> 1][h], bf[nj >> 1][h + 2]);
                }
            }
        }
        __syncthreads();
    }

    // epilogue: bias, scale, fp16 single out
    const int lr = lane >> 2;
    const int lc = (lane & 3) * 2;
#pragma unroll
    for (int nj = 0; nj < 4; nj++) {
        const int c = bn + wn * 32 + nj * 8 + lc;
        const float b0 = bias[c], b1 = bias[c + 1];
#pragma unroll
        for (int mi = 0; mi < 4; mi++) {
            const int r = bm + wm * 64 + mi * 16 + lr;
            float v0 = acc[mi][nj][0] + b0, v1 = acc[mi][nj][1] + b1;
            float v2 = acc[mi][nj][2] + b0, v3 = acc[mi][nj][3] + b1;
            *(uint32_t*)&out[(size_t)r * CC + c] = packh2(v0 * scale, v1 * scale);
            *(uint32_t*)&out[(size_t)(r + 8) * CC + c] = packh2(v2 * scale, v3 * scale);
        }
    }
}

// ================================================================================
// Output projection GEMM: R15 variant — 8 warps as m16-strips x n128.
// 1-term fp16, yh @ Wp^T -> fp32 out. (measured 59.6us)
// ================================================================================
__global__ __launch_bounds__(256) void proj_mma_kernel(
    const __half* __restrict__ Ah, const __half* __restrict__ B,
    float* __restrict__ Cf)
{
    extern __shared__ char smem[];
    const uint32_t sbase = smem_u32(smem);
    const int tid = threadIdx.x;
    const int wid = tid >> 5;
    const int lane = tid & 31;
    const int bm = blockIdx.y * 128;
    const int bn = blockIdx.x * 128;

    const int lrow = (lane & 7) + ((lane >> 3) & 1) * 8;
    const int lkb = (lane >> 4) * 16;

    float acc[16][4];
#pragma unroll
    for (int a = 0; a < 16; a++)
#pragma unroll
        for (int c = 0; c < 4; c++) acc[a][c] = 0.0f;

    auto load_chunk = [&](int chunk, int buf) {
        const int k0 = chunk * KC;
        const uint32_t tbu = sbase + buf * 2 * TILE_B;
#pragma unroll
        for (int part = 0; part < 2; part++) {
            const __half* p = part ? B : Ah;
            const int roff = part ? bn : bm;
            const uint32_t db = tbu + part * TILE_B;
#pragma unroll
            for (int f = tid; f < 1024; f += 256) {
                int row = f >> 3;
                int c16 = f & 7;
                cp16(db + SWZ(row, c16 * 16),
                     p + (size_t)(roff + row) * CC + k0 + c16 * 8);
            }
        }
        CP_COMMIT();
    };

    load_chunk(0, 0);

    for (int chunk = 0; chunk < NCHUNK; chunk++) {
        const int buf = chunk & 1;
        if (chunk + 1 < NCHUNK) {
            load_chunk(chunk + 1, buf ^ 1);
            CP_WAIT(1);
        } else {
            CP_WAIT(0);
        }
        __syncthreads();

        const uint32_t tA = sbase + buf * 2 * TILE_B;
        const uint32_t tB = tA + TILE_B;

#pragma unroll
        for (int ks = 0; ks < 4; ks++) {
            const int kb = ks * 32;
            uint32_t af[4];
            ldm_x4(af, tA + SWZ(wid * 16 + lrow, kb + lkb));
#pragma unroll
            for (int nh = 0; nh < 2; nh++) {
                uint32_t bf[4][4];
#pragma unroll
                for (int nj2 = 0; nj2 < 4; nj2++)
                    ldm_x4(bf[nj2], tB + SWZ(nh * 64 + nj2 * 16 + lrow, kb + lkb));
#pragma unroll
                for (int nj2 = 0; nj2 < 4; nj2++) {
#pragma unroll
                    for (int hh = 0; hh < 2; hh++) {
                        mma_f16(acc[nh * 8 + nj2 * 2 + hh], af,
                                bf[nj2][hh], bf[nj2][hh + 2]);
                    }
                }
            }
        }
        __syncthreads();
    }

    const int lr = lane >> 2;
    const int lc = (lane & 3) * 2;
    const int r = bm + wid * 16 + lr;
#pragma unroll
    for (int nj = 0; nj < 16; nj++) {
        const int c = bn + nj * 8 + lc;
        *(float2*)&Cf[(size_t)r * CC + c] = make_float2(acc[nj][0], acc[nj][1]);
        *(float2*)&Cf[(size_t)(r + 8) * CC + c] = make_float2(acc[nj][2], acc[nj][3]);
    }
}

// ================================================================================
// Flash attention via mma.sync, all-single fp16 operands (Q, K, V, P).
// Q is pre-scaled into log2 domain -> softmax uses raw ex2. (champion verbatim)
// ================================================================================
#define ATT_SMEM 49152

__global__ __launch_bounds__(256) void attn_mma_kernel(
    const __half* __restrict__ qh, const __half* __restrict__ kh,
    const __half* __restrict__ vh, __half* __restrict__ yh)
{
    extern __shared__ char smem[];
    const uint32_t sb = smem_u32(smem);
    const uint32_t sQ = sb;
    const uint32_t sKV = sb + 16384;   // + buf*16384: K@0, V@8192

    const int tid = threadIdx.x;
    const int wid = tid >> 5;
    const int lane = tid & 31;
    const int lrow = (lane & 7) + ((lane >> 3) & 1) * 8;
    const int lkb = (lane >> 4) * 16;

    // heavy-first: largest qt launches earliest
    const int qt = (gridDim.x - 1) - blockIdx.x;
    const int q0 = qt * 128;
    const int bh = blockIdx.y;
    const int b = bh >> 4;
    const int h = bh & 15;
    const size_t base = (size_t)b * TT * CC + (size_t)h * HD;

#pragma unroll
    for (int f = tid; f < 1024; f += 256) {
        int row = f >> 3, c16 = f & 7;
        cp16(sQ + SWZ(row, c16 * 16), qh + base + (size_t)(q0 + row) * CC + c16 * 8);
    }

    const __half* kvsrc[2] = {kh, vh};
    auto load_kv = [&](int kt, int buf) {
        const uint32_t db = sKV + buf * 16384;
#pragma unroll
        for (int f = tid; f < 1024; f += 256) {
            int mat = f >> 9, idx = f & 511;
            int row = idx >> 3, c16 = idx & 7;
            cp16(db + mat * 8192 + SWZ(row, c16 * 16),
                 kvsrc[mat] + base + (size_t)(kt * 64 + row) * CC + c16 * 8);
        }
    };

    const int nkt = 2 * (qt + 1);
    load_kv(0, 0);
    CP_COMMIT();

    float m0 = -3.0e38f, m1 = -3.0e38f, l0 = 0.0f, l1 = 0.0f;
    float o[8][4];
#pragma unroll
    for (int nt = 0; nt < 8; nt++)
#pragma unroll
        for (int c = 0; c < 4; c++) o[nt][c] = 0.0f;

    const int q0w = q0 + 16 * wid;

    for (int kt = 0; kt < nkt; kt++) {
        const int buf = kt & 1;
        if (kt + 1 < nkt) {
            load_kv(kt + 1, buf ^ 1);
            CP_COMMIT();
            CP_WAIT(1);
        } else {
            CP_WAIT(0);
        }
        __syncthreads();

        const int kc = kt * 64;
        if (kc <= q0w + 15) {
            const uint32_t bK = sKV + buf * 16384;
            const uint32_t bV = bK + 8192;

            // ---- S = Q K^T (single fp16, log2 domain) ----
            float s[8][4];
#pragma unroll
            for (int nt = 0; nt < 8; nt++)
#pragma unroll
                for (int c = 0; c < 4; c++) s[nt][c] = 0.0f;

#pragma unroll
            for (int ks = 0; ks < 4; ks++) {
                const int kb = ks * 32;
                uint32_t a[4];
                ldm_x4(a, sQ + SWZ(16 * wid + lrow, kb + lkb));
#pragma unroll
                for (int nt2 = 0; nt2 < 4; nt2++) {
                    uint32_t bhf[4];
                    ldm_x4(bhf, bK + SWZ(nt2 * 16 + lrow, kb + lkb));
#pragma unroll
                    for (int hh = 0; hh < 2; hh++) {
                        mma_f16(s[nt2 * 2 + hh], a, bhf[hh], bhf[hh + 2]);
                    }
                }
            }

            // ---- causal mask on diagonal tiles ----
            if (kc + 63 > q0w) {
                const int r0 = q0w + (lane >> 2);
                const int r1 = r0 + 8;
#pragma unroll
                for (int nt = 0; nt < 8; nt++) {
                    int c0 = kc + 8 * nt + 2 * (lane & 3);
                    if (c0 > r0)     s[nt][0] = -1.0e30f;
                    if (c0 + 1 > r0) s[nt][1] = -1.0e30f;
                    if (c0 > r1)     s[nt][2] = -1.0e30f;
                    if (c0 + 1 > r1) s[nt][3] = -1.0e30f;
                }
            }

            // ---- online softmax (ex2; s already in log2 domain) ----
            float mt0 = -3.0e38f, mt1 = -3.0e38f;
#pragma unroll
            for (int nt = 0; nt < 8; nt++) {
                mt0 = fmaxf(mt0, fmaxf(s[nt][0], s[nt][1]));
                mt1 = fmaxf(mt1, fmaxf(s[nt][2], s[nt][3]));
            }
#pragma unroll
            for (int d = 1; d <= 2; d <<= 1) {
                mt0 = fmaxf(mt0, __shfl_xor_sync(0xffffffffu, mt0, d));
                mt1 = fmaxf(mt1, __shfl_xor_sync(0xffffffffu, mt1, d));
            }
            float mn0 = fmaxf(m0, mt0), mn1 = fmaxf(m1, mt1);
            float corr0 = ex2(m0 - mn0), corr1 = ex2(m1 - mn1);
            float ls0 = 0.0f, ls1 = 0.0f;
#pragma unroll
            for (int nt = 0; nt < 8; nt++) {
                s[nt][0] = ex2(s[nt][0] - mn0);
                s[nt][1] = ex2(s[nt][1] - mn0);
                s[nt][2] = ex2(s[nt][2] - mn1);
                s[nt][3] = ex2(s[nt][3] - mn1);
                ls0 += s[nt][0] + s[nt][1];
                ls1 += s[nt][2] + s[nt][3];
            }
#pragma unroll
            for (int d = 1; d <= 2; d <<= 1) {
                ls0 += __shfl_xor_sync(0xffffffffu, ls0, d);
                ls1 += __shfl_xor_sync(0xffffffffu, ls1, d);
            }
            l0 = l0 * corr0 + ls0;  m0 = mn0;
            l1 = l1 * corr1 + ls1;  m1 = mn1;
#pragma unroll
            for (int nt = 0; nt < 8; nt++) {
                o[nt][0] *= corr0; o[nt][1] *= corr0;
                o[nt][2] *= corr1; o[nt][3] *= corr1;
            }

            // ---- O += P V (single fp16) ----
#pragma unroll
            for (int ks = 0; ks < 4; ks++) {
                uint32_t a[4];
                a[0] = packh2(s[2 * ks][0], s[2 * ks][1]);
                a[1] = packh2(s[2 * ks][2], s[2 * ks][3]);
                a[2] = packh2(s[2 * ks + 1][0], s[2 * ks + 1][1]);
                a[3] = packh2(s[2 * ks + 1][2], s[2 * ks + 1][3]);
#pragma unroll
                for (int nt2 = 0; nt2 < 4; nt2++) {
                    uint32_t bvh[4];
                    ldm_x4_t(bvh, bV + SWZ(ks * 16 + lrow, nt2 * 32 + lkb));
#pragma unroll
                    for (int hh = 0; hh < 2; hh++) {
                        mma_f16(o[nt2 * 2 + hh], a, bvh[2 * hh], bvh[2 * hh + 1]);
                    }
                }
            }
        }
        __syncthreads();
    }

    // ---- normalize, store single fp16 ----
    const float inv0 = 1.0f / l0, inv1 = 1.0f / l1;
    const int t0 = q0w + (lane >> 2);
    const int t1 = t0 + 8;
#pragma unroll
    for (int nt = 0; nt < 8; nt++) {
        const int c = 8 * nt + 2 * (lane & 3);
        *(uint32_t*)&yh[base + (size_t)t0 * CC + c] =
            packh2(o[nt][0] * inv0, o[nt][1] * inv0);
        *(uint32_t*)&yh[base + (size_t)t1 * CC + c] =
            packh2(o[nt][2] * inv1, o[nt][3] * inv1);
    }
}

// ================================================================================
// launch
// ================================================================================
extern "C" void kernel_launch(void* const* d_in, const int* in_sizes, int n_in,
                              void* d_out, int out_size)
{
    const float* x  = (const float*)d_in[0];
    const float* Wq = (const float*)d_in[1];
    const float* bq = (const float*)d_in[2];
    const float* Wk = (const float*)d_in[3];
    const float* bk = (const float*)d_in[4];
    const float* Wv = (const float*)d_in[5];
    const float* bv = (const float*)d_in[6];
    const float* Wp = (const float*)d_in[7];
    float* out = (float*)d_out;

    __half *xh, *qh, *kh, *vh, *yh, *w;
    cudaGetSymbolAddress((void**)&xh, g_xh);
    cudaGetSymbolAddress((void**)&qh, g_qh);
    cudaGetSymbolAddress((void**)&kh, g_kh);
    cudaGetSymbolAddress((void**)&vh, g_vh);
    cudaGetSymbolAddress((void**)&yh, g_yh);
    cudaGetSymbolAddress((void**)&w,  g_w);

    cudaFuncSetAttribute(qkv_mma_kernel, cudaFuncAttributeMaxDynamicSharedMemorySize,
                         SMEM_G);
    cudaFuncSetAttribute(proj_mma_kernel, cudaFuncAttributeMaxDynamicSharedMemorySize,
                         SMEM_G);
    cudaFuncSetAttribute(attn_mma_kernel, cudaFuncAttributeMaxDynamicSharedMemorySize,
                         ATT_SMEM);

    // merged conversions: x + all 4 weights in ONE launch
    conv_all_kernel<<<NB_ALL, 256>>>(x, Wq, Wk, Wv, Wp, xh, w);

    // fused QKV projections: R14 champion warp layout (2m x 4n, 64x32)
    qkv_mma_kernel<<<dim3(24, MM / 128), 256, SMEM_G>>>(xh, w, bq, bk, bv,
                                                        qh, kh, vh);

    // attention (tensor-core fp16, heavy-first, ex2 softmax) — champion verbatim
    attn_mma_kernel<<<dim3(TT / 128, BB * HH), 256, ATT_SMEM>>>(qh, kh, vh, yh);

    // output projection: R15 warp layout (m16-strips x n128) — measured faster
    proj_mma_kernel<<<dim3(CC / 128, MM / 128), 256, SMEM_G>>>(yh, w + 3 * WSZ, out);
}